// round 14
// baseline (speedup 1.0000x reference)
#include <cuda_runtime.h>

#define N2   2048
#define NPIX (N2*N2)
#define CAP  65536
#define CW_WARPS 4096
#define RW   128
#define MARGIN 6144

// ---------------- device scratch (static allocation only) ----------------
__device__ float    d_u[NPIX];           // combined conv output  (16.8 MB)
__device__ unsigned d_keys[NPIX];        // monotonic keys        (16.8 MB)
__device__ float    d_cw[80];            // weff[72], beff, db (gate path)
__device__ unsigned d_hist1[4096];
__device__ unsigned d_hist2[4096];
__device__ unsigned d_sel[8];            // [0]=b1 [1]=needed1 [2]=thrKey [3]=C
__device__ unsigned d_warpCnt[CW_WARPS];
__device__ unsigned d_warpOff[CW_WARPS];
__device__ unsigned d_ci[2][CAP];        // candidate ~key (ping-pong)
__device__ unsigned d_cx[2][CAP];        // payload = candidate slot (ping-pong)
__device__ unsigned d_cpix[CAP];         // slot -> pixel idx
__device__ float    d_csym[CAP * 8];     // slot -> sym[8] (2 MB)
__device__ unsigned d_wh[RW * 256];      // radix per-warp hist
__device__ unsigned d_woff[RW * 256];    // radix per-warp scatter offsets
__device__ volatile unsigned d_bar;      // grid barrier counter (reset by k_init)

// ---------------- init: zero control state + combine gate weights ----------------
__global__ void k_init(const float* __restrict__ ws, const float* __restrict__ bs,
                       const float* __restrict__ w0, const float* __restrict__ b0,
                       const float* __restrict__ w1, const float* __restrict__ b1) {
    int t = blockIdx.x * 1024 + threadIdx.x;
    if (t < 4096)       d_hist1[t] = 0u;
    else if (t < 8192)  d_hist2[t - 4096] = 0u;
    else if (t < 8200)  d_sel[t - 8192] = 0u;
    else if (t == 8200) *(unsigned*)&d_bar = 0u;
    if (blockIdx.x == 0) {
        __shared__ float sa[8];
        int tid = threadIdx.x;
        if (tid < 8) sa[tid] = ws[8 + tid] - ws[tid];
        __syncthreads();
        if (tid < 72) {
            float s = 0.f;
            #pragma unroll
            for (int e = 0; e < 4; e++)
                s += sa[e] * w0[e * 72 + tid] + sa[4 + e] * w1[e * 72 + tid];
            d_cw[tid] = s;
        } else if (tid == 72) {
            float s = 0.f;
            #pragma unroll
            for (int e = 0; e < 4; e++) s += sa[e] * b0[e] + sa[4 + e] * b1[e];
            d_cw[72] = s;
        } else if (tid == 73) {
            d_cw[73] = bs[1] - bs[0];
        }
    }
}

// ---------------- single-channel 3x3 conv with combined weights (R9, measured) ----
__global__ void k_conv(const float* __restrict__ rel) {
    __shared__ float s[34][36];
    __shared__ float wsm[74];
    int tx = threadIdx.x, ty = threadIdx.y;
    int tid = ty * 32 + tx;
    if (tid < 74) wsm[tid] = d_cw[tid];
    int x0 = blockIdx.x * 32, y0 = blockIdx.y * 32;
    float acc[4] = {0.f, 0.f, 0.f, 0.f};
    for (int c = 0; c < 8; c++) {
        __syncthreads();
        const float* rc = rel + (size_t)c * NPIX;
        for (int t = tid; t < 34 * 34; t += 256) {
            int r = t / 34, cc = t - r * 34;
            int gy = y0 - 1 + r, gx = x0 - 1 + cc;
            float v = 0.f;
            if ((unsigned)gy < N2 && (unsigned)gx < N2) v = rc[gy * N2 + gx];
            s[r][cc] = v;
        }
        __syncthreads();
        const float* wc = &wsm[c * 9];
        #pragma unroll
        for (int rr = 0; rr < 4; rr++) {
            int row = ty + rr * 8;
            float a = acc[rr];
            #pragma unroll
            for (int dy = 0; dy < 3; dy++)
                #pragma unroll
                for (int dx = 0; dx < 3; dx++)
                    a += s[row + dy][tx + dx] * wc[dy * 3 + dx];
            acc[rr] = a;
        }
    }
    float be = wsm[72];
    #pragma unroll
    for (int rr = 0; rr < 4; rr++) {
        int row = ty + rr * 8;
        d_u[(y0 + row) * N2 + x0 + tx] = acc[rr] + be;
    }
}

// ---------------- symmetrize + key + hist1: batched loads + match-agg atomics ----
// All lanes ALWAYS execute __match_any_sync (no divergent continue): NEG-key
// lanes contribute singleton value 0x1000+lane (disjoint from bins 0..4095).
__global__ void k_symkey() {
    __shared__ float sB[64][65];
    __shared__ unsigned sh[4096];
    int tid = threadIdx.x;
    for (int i = tid; i < 4096; i += 256) sh[i] = 0u;
    int x0 = blockIdx.x * 64, y0 = blockIdx.y * 64;
    int ld = tid & 63, rr = tid >> 6;
    for (int r = rr; r < 64; r += 4)
        sB[r][ld] = d_u[(x0 + r) * N2 + y0 + ld];
    __syncthreads();
    float db = d_cw[73];
    unsigned NEGK = ~__float_as_uint(-1e30f);
    int lane = tid & 31;

    // phase 1: batch all 16 direct loads (MLP=16)
    float av[16];
    #pragma unroll
    for (int q = 0; q < 16; q++) {
        int r = rr + q * 4;
        av[q] = d_u[(y0 + r) * N2 + x0 + ld];
    }
    // phase 2: keys + coalesced stores + warp-aggregated smem histogram
    unsigned neg = 0;
    #pragma unroll
    for (int q = 0; q < 16; q++) {
        int r = rr + q * 4;
        float w = 0.5f * (av[q] + sB[ld][r]) + db;
        float m = (w > 0.f) ? w : -1e30f;
        unsigned bits = __float_as_uint(m);
        unsigned key  = ((int)bits < 0) ? ~bits : (bits | 0x80000000u);
        d_keys[(y0 + r) * N2 + x0 + ld] = key;
        bool isneg = (key == NEGK);
        unsigned bin = key >> 20;
        unsigned mv  = isneg ? (0x1000u + (unsigned)lane) : bin;
        unsigned msk = __match_any_sync(0xffffffffu, mv);
        if (!isneg && (int)(__ffs(msk) - 1) == lane) atomicAdd(&sh[bin], __popc(msk));
        if (isneg) neg++;
    }
    if (neg) atomicAdd(&sh[NEGK >> 20], neg);
    __syncthreads();
    for (int b = tid; b < 4096; b += 256) {
        unsigned c = sh[b];
        if (c) atomicAdd(&d_hist1[b], c);
    }
}

// ---------------- descending-cumulative threshold pick (mode 0/1) ----------------
__global__ void k_choose(int mode, unsigned Kv) {
    __shared__ unsigned ts[1024];
    const unsigned* hist = mode ? d_hist2 : d_hist1;
    int t = threadIdx.x;
    unsigned target = (mode == 0) ? Kv : d_sel[1];
    unsigned r[4]; unsigned lsum = 0;
    #pragma unroll
    for (int jj = 0; jj < 4; jj++) { r[jj] = hist[4095 - (t * 4 + jj)]; lsum += r[jj]; }
    ts[t] = lsum; __syncthreads();
    for (int off = 1; off < 1024; off <<= 1) {
        unsigned v = (t >= off) ? ts[t - off] : 0u;
        __syncthreads();
        ts[t] += v;
        __syncthreads();
    }
    unsigned run = ts[t] - lsum;
    #pragma unroll
    for (int jj = 0; jj < 4; jj++) {
        unsigned prev = run; run += r[jj];
        if (prev < target && run >= target) {
            unsigned b = 4095 - (t * 4 + jj);
            if (mode == 0) { d_sel[0] = b; d_sel[1] = target - prev; }
            else           { unsigned b1 = d_sel[0]; d_sel[2] = ((b1 << 12) | b) << 8; }
        }
    }
}

// ---------------- second-level histogram (R9 version: MLP=8 strided) ----------------
__global__ void k_hist2() {
    unsigned b1 = d_sel[0];
    int base = blockIdx.x * 2048 + threadIdx.x;
    #pragma unroll
    for (int i = 0; i < 8; i++) {
        unsigned key = d_keys[base + i * 256];
        if ((key >> 20) == b1) atomicAdd(&d_hist2[(key >> 8) & 0xFFFu], 1u);
    }
}

// ---------------- ordered compaction: count / scan / write ----------------
__global__ void k_ccount() {
    unsigned thr = d_sel[2];
    int w = blockIdx.x * 8 + (threadIdx.x >> 5);
    int lane = threadIdx.x & 31;
    const uint4* kp = (const uint4*)d_keys;
    int base = w * 256 + lane;   // uint4 units; warp covers 1024 keys
    unsigned cnt = 0;
    #pragma unroll
    for (int r = 0; r < 8; r++) {
        uint4 kv = kp[base + r * 32];
        cnt += (kv.x >= thr) + (kv.y >= thr) + (kv.z >= thr) + (kv.w >= thr);
    }
    cnt = __reduce_add_sync(0xffffffffu, cnt);
    if (lane == 0) d_warpCnt[w] = cnt;
}

__global__ void k_cscan() {
    __shared__ unsigned ts[1024];
    int t = threadIdx.x;
    unsigned r[4], l = 0;
    #pragma unroll
    for (int jj = 0; jj < 4; jj++) { r[jj] = d_warpCnt[t * 4 + jj]; l += r[jj]; }
    ts[t] = l; __syncthreads();
    for (int off = 1; off < 1024; off <<= 1) {
        unsigned v = (t >= off) ? ts[t - off] : 0u;
        __syncthreads();
        ts[t] += v;
        __syncthreads();
    }
    unsigned base = ts[t] - l;
    #pragma unroll
    for (int jj = 0; jj < 4; jj++) { d_warpOff[t * 4 + jj] = base; base += r[jj]; }
    if (t == 1023) d_sel[3] = (base > CAP) ? CAP : base;
}

__global__ void k_cwrite() {
    unsigned thr = d_sel[2];
    int w = blockIdx.x * 8 + (threadIdx.x >> 5);
    int lane = threadIdx.x & 31;
    unsigned run = d_warpOff[w];
    int base = w * 1024;
    for (int r = 0; r < 32; r++) {
        int e = base + r * 32 + lane;
        unsigned key = d_keys[e];
        bool p = key >= thr;
        unsigned mask = __ballot_sync(0xffffffffu, p);
        if (p) {
            unsigned pos = run + __popc(mask & ((1u << lane) - 1u));
            if (pos < CAP) {
                d_ci[0][pos]  = ~key;
                d_cx[0][pos]  = pos;          // payload = slot
                d_cpix[pos]   = (unsigned)e;  // slot -> pixel
            }
        }
        run += __popc(mask);
    }
}

// ---------------- reference-faithful evaluation (verified bit-exact R8-R10) ----------
__device__ __forceinline__ float ldpix(const float* __restrict__ rel, int c, int y, int x) {
    bool ok = ((unsigned)y < N2) & ((unsigned)x < N2);
    int yy = ok ? y : 0;
    int xx = ok ? x : 0;
    float v = __ldg(&rel[(size_t)c * NPIX + yy * N2 + xx]);
    return ok ? v : 0.f;
}

__device__ __forceinline__ void faithful_eval(
    const float* __restrict__ rel,
    const float* w0s, const float* w1s,
    const float* bsm, const float* wssm, const float* bssm,
    int i, int j, float sym[8], float* l0o, float* l1o)
{
    float accA[8], accB[8];
    #pragma unroll
    for (int e = 0; e < 8; e++) { accA[e] = 0.f; accB[e] = 0.f; }
    #pragma unroll
    for (int dy = 0; dy < 3; dy++) {
        #pragma unroll
        for (int dx = 0; dx < 3; dx++) {
            int y1 = i + dy - 1, x1 = j + dx - 1;
            int y2 = j + dy - 1, x2 = i + dx - 1;
            #pragma unroll
            for (int c = 0; c < 8; c++) {
                float v1 = ldpix(rel, c, y1, x1);
                float v2 = ldpix(rel, c, y2, x2);
                int tap = (dy * 3 + dx) * 8 + c;
                #pragma unroll
                for (int e = 0; e < 4; e++) {
                    accA[e]     = fmaf(v1, w0s[e * 72 + tap], accA[e]);
                    accA[4 + e] = fmaf(v1, w1s[e * 72 + tap], accA[4 + e]);
                    accB[e]     = fmaf(v2, w0s[e * 72 + tap], accB[e]);
                    accB[4 + e] = fmaf(v2, w1s[e * 72 + tap], accB[4 + e]);
                }
            }
        }
    }
    #pragma unroll
    for (int e = 0; e < 8; e++) {
        float sA = accA[e] + bsm[e];
        float sB = accB[e] + bsm[e];
        sym[e] = (sA + sB) * 0.5f;
    }
    float l0 = 0.f, l1 = 0.f;
    #pragma unroll
    for (int e = 0; e < 8; e++) l0 = fmaf(sym[e], wssm[e], l0);
    l0 = l0 + bssm[0];
    #pragma unroll
    for (int e = 0; e < 8; e++) l1 = fmaf(sym[e], wssm[8 + e], l1);
    l1 = l1 + bssm[1];
    *l0o = l0; *l1o = l1;
}

__device__ __forceinline__ void load_weights_sw(
    const float* __restrict__ w0, const float* __restrict__ w1,
    const float* __restrict__ b0, const float* __restrict__ b1,
    const float* __restrict__ ws, const float* __restrict__ bs,
    float* w0s, float* w1s, float* bsm, float* wssm, float* bssm, int tid, int nthr)
{
    for (int t = tid; t < 288; t += nthr) {
        int e = t / 72, r = t - e * 72;
        int dyx = r >> 3, c = r & 7;
        int src = e * 72 + c * 9 + dyx;
        w0s[t] = w0[src];
        w1s[t] = w1[src];
    }
    if (tid < 4)  { bsm[tid] = b0[tid]; bsm[4 + tid] = b1[tid]; }
    if (tid >= 4 && tid < 20) wssm[tid - 4] = ws[tid - 4];
    if (tid >= 20 && tid < 22) bssm[tid - 20] = bs[tid - 20];
}

// rewrite candidate keys with exact values; store sym[8] per slot for emit
__global__ void k_refine(const float* __restrict__ rel,
                         const float* __restrict__ w0, const float* __restrict__ b0,
                         const float* __restrict__ w1, const float* __restrict__ b1,
                         const float* __restrict__ ws, const float* __restrict__ bs) {
    __shared__ float w0s[288], w1s[288], bsm[8], wssm[16], bssm[2];
    int tid = threadIdx.x;
    load_weights_sw(w0, w1, b0, b1, ws, bs, w0s, w1s, bsm, wssm, bssm, tid, 128);
    __syncthreads();
    unsigned C = d_sel[3];
    unsigned k = blockIdx.x * 128 + tid;
    if (k >= C) return;
    unsigned idx = d_cpix[k];
    int i = (int)(idx >> 11), j = (int)(idx & 2047u);
    float sym[8], l0, l1;
    faithful_eval(rel, w0s, w1s, bsm, wssm, bssm, i, j, sym, &l0, &l1);
    float v = (l1 > l0) ? (l1 - l0) : -1e30f;
    unsigned bits = __float_as_uint(v);
    unsigned key  = ((int)bits < 0) ? ~bits : (bits | 0x80000000u);
    d_ci[0][k] = ~key;
    #pragma unroll
    for (int e = 0; e < 8; e++) d_csym[k * 8 + e] = sym[e];
}

// ---------------- single-kernel stable LSD radix sort (16 blocks, grid barrier) ----
// 16 blocks always co-resident on 148 SMs -> hand-rolled barrier is deadlock-free.
__device__ __forceinline__ void grid_bar(unsigned* target) {
    __syncthreads();
    __threadfence();
    if (threadIdx.x == 0) {
        atomicAdd((unsigned*)&d_bar, 1u);
        while (d_bar < *target) { __nanosleep(20); }
    }
    __syncthreads();
    __threadfence();
    *target += 16;
}

__global__ __launch_bounds__(256) void k_sort() {
    __shared__ unsigned sh[8][256];
    __shared__ unsigned ts[256];
    int warp = threadIdx.x >> 5, lane = threadIdx.x & 31;
    int w = blockIdx.x * 8 + warp;
    unsigned C = d_sel[3];
    unsigned base = (unsigned)w * 512u;
    unsigned target = 16;
    int s = 0;
    for (int p = 0; p < 4; p++) {
        // --- per-warp histogram ---
        for (int d = lane; d < 256; d += 32) sh[warp][d] = 0u;
        __syncwarp();
        for (int r = 0; r < 16; r++) {
            unsigned e = base + r * 32 + lane;
            if (e < C) {
                unsigned d = (d_ci[s][e] >> (p * 8)) & 255u;
                atomicAdd(&sh[warp][d], 1u);
            }
        }
        __syncwarp();
        for (int d = lane; d < 256; d += 32) d_wh[w * 256 + d] = sh[warp][d];
        grid_bar(&target);
        // --- scan (block 0 only) ---
        if (blockIdx.x == 0) {
            int t = threadIdx.x;
            unsigned tot = 0;
            for (int ww = 0; ww < RW; ww++) tot += d_wh[ww * 256 + t];
            ts[t] = tot; __syncthreads();
            for (int off = 1; off < 256; off <<= 1) {
                unsigned v = (t >= off) ? ts[t - off] : 0u;
                __syncthreads();
                ts[t] += v;
                __syncthreads();
            }
            unsigned run = ts[t] - tot;
            for (int ww = 0; ww < RW; ww++) { d_woff[ww * 256 + t] = run; run += d_wh[ww * 256 + t]; }
        }
        grid_bar(&target);
        // --- scatter ---
        for (int d = lane; d < 256; d += 32) sh[warp][d] = d_woff[w * 256 + d];
        __syncwarp();
        int ds = 1 - s;
        for (int r = 0; r < 16; r++) {
            unsigned e = base + r * 32 + lane;
            bool act = (e < C);
            unsigned inv = 0, d = 0, idx = 0;
            if (act) { inv = d_ci[s][e]; idx = d_cx[s][e]; d = (inv >> (p * 8)) & 255u; }
            unsigned mv = act ? d : (0x100u | (unsigned)lane);
            unsigned mask = __match_any_sync(0xffffffffu, mv);
            unsigned rank = __popc(mask & ((1u << lane) - 1u));
            unsigned dst = 0;
            if (act) dst = sh[warp][d] + rank;
            __syncwarp();
            if (act && rank == 0) sh[warp][d] += __popc(mask);
            __syncwarp();
            if (act) { d_ci[ds][dst] = inv; d_cx[ds][dst] = idx; }
        }
        s = ds;
        if (p < 3) grid_bar(&target);
    }
}

// ---------------- emit: pure gather (sym precomputed in refine) ----------------
__global__ void k_emit(float* __restrict__ out, int K) {
    int k = blockIdx.x * 128 + threadIdx.x;
    if (k >= K) return;
    unsigned inv = d_ci[0][k];
    unsigned key = ~inv;
    float val = (key & 0x80000000u) ? __uint_as_float(key ^ 0x80000000u)
                                    : __uint_as_float(~key);
    unsigned slot = d_cx[0][k];
    unsigned idx  = d_cpix[slot];
    int i = (int)(idx >> 11), j = (int)(idx & 2047u);
    out[k]         = (float)i;
    out[K + k]     = (float)j;
    out[2 * K + k] = val;
    #pragma unroll
    for (int e = 0; e < 8; e++)
        out[3 * K + e * K + k] = d_csym[slot * 8 + e];
}

// ---------------- launch ----------------
extern "C" void kernel_launch(void* const* d_in, const int* in_sizes, int n_in,
                              void* d_out, int out_size) {
    const float* rel = (const float*)d_in[0];
    const float* w0  = (const float*)d_in[1];
    const float* b0  = (const float*)d_in[2];
    const float* w1  = (const float*)d_in[3];
    const float* b1  = (const float*)d_in[4];
    const float* ws  = (const float*)d_in[5];
    const float* bs  = (const float*)d_in[6];
    float* out = (float*)d_out;
    int K = out_size / 11;                    // [2,K]+[K]+[8,K] = 11K floats

    k_init<<<9, 1024>>>(ws, bs, w0, b0, w1, b1);
    k_conv<<<dim3(64, 64), dim3(32, 8)>>>(rel);
    k_symkey<<<dim3(32, 32), 256>>>();
    k_choose<<<1, 1024>>>(0, (unsigned)(K + MARGIN));
    k_hist2<<<2048, 256>>>();
    k_choose<<<1, 1024>>>(1, 0u);
    k_ccount<<<512, 256>>>();
    k_cscan<<<1, 1024>>>();
    k_cwrite<<<512, 256>>>();
    k_refine<<<(CAP + 127) / 128, 128>>>(rel, w0, b0, w1, b1, ws, bs);
    k_sort<<<16, 256>>>();
    k_emit<<<(K + 127) / 128, 128>>>(out, K);
}

// round 15
// speedup vs baseline: 1.7430x; 1.7430x over previous
#include <cuda_runtime.h>

#define N2   2048
#define NPIX (N2*N2)
#define CAP  65536
#define CW_WARPS 4096
#define RW   128
#define MARGIN 6144

// ---------------- device scratch (static allocation only) ----------------
__device__ float    d_u[NPIX];           // combined conv output  (16.8 MB)
__device__ unsigned d_keys[NPIX];        // monotonic keys        (16.8 MB)
__device__ float    d_cw[80];            // weff[72], beff, db (gate path)
__device__ unsigned d_hist1[4096];
__device__ unsigned d_hist2[4096];
__device__ unsigned d_sel[8];            // [0]=b1 [1]=needed1 [2]=thrKey [3]=C
__device__ unsigned d_warpCnt[CW_WARPS];
__device__ unsigned d_warpOff[CW_WARPS];
__device__ unsigned d_ci[2][CAP];        // candidate ~key (ping-pong)
__device__ unsigned d_cx[2][CAP];        // payload = candidate slot (ping-pong)
__device__ unsigned d_cpix[CAP];         // slot -> pixel idx
__device__ float    d_csym[CAP * 8];     // slot -> sym[8] (2 MB)
__device__ unsigned d_wh[RW * 256];      // radix per-warp hist
__device__ unsigned d_woff[RW * 256];    // radix per-warp scatter offsets

// ---------------- init: zero control state + combine gate weights ----------------
__global__ void k_init(const float* __restrict__ ws, const float* __restrict__ bs,
                       const float* __restrict__ w0, const float* __restrict__ b0,
                       const float* __restrict__ w1, const float* __restrict__ b1) {
    int t = blockIdx.x * 1024 + threadIdx.x;
    if (t < 4096)       d_hist1[t] = 0u;
    else if (t < 8192)  d_hist2[t - 4096] = 0u;
    else if (t < 8200)  d_sel[t - 8192] = 0u;
    if (blockIdx.x == 0) {
        __shared__ float sa[8];
        int tid = threadIdx.x;
        if (tid < 8) sa[tid] = ws[8 + tid] - ws[tid];
        __syncthreads();
        if (tid < 72) {
            float s = 0.f;
            #pragma unroll
            for (int e = 0; e < 4; e++)
                s += sa[e] * w0[e * 72 + tid] + sa[4 + e] * w1[e * 72 + tid];
            d_cw[tid] = s;
        } else if (tid == 72) {
            float s = 0.f;
            #pragma unroll
            for (int e = 0; e < 4; e++) s += sa[e] * b0[e] + sa[4 + e] * b1[e];
            d_cw[72] = s;
        } else if (tid == 73) {
            d_cw[73] = bs[1] - bs[0];
        }
    }
}

// ---------------- single-channel 3x3 conv with combined weights (R9, measured) ----
__global__ void k_conv(const float* __restrict__ rel) {
    __shared__ float s[34][36];
    __shared__ float wsm[74];
    int tx = threadIdx.x, ty = threadIdx.y;
    int tid = ty * 32 + tx;
    if (tid < 74) wsm[tid] = d_cw[tid];
    int x0 = blockIdx.x * 32, y0 = blockIdx.y * 32;
    float acc[4] = {0.f, 0.f, 0.f, 0.f};
    for (int c = 0; c < 8; c++) {
        __syncthreads();
        const float* rc = rel + (size_t)c * NPIX;
        for (int t = tid; t < 34 * 34; t += 256) {
            int r = t / 34, cc = t - r * 34;
            int gy = y0 - 1 + r, gx = x0 - 1 + cc;
            float v = 0.f;
            if ((unsigned)gy < N2 && (unsigned)gx < N2) v = rc[gy * N2 + gx];
            s[r][cc] = v;
        }
        __syncthreads();
        const float* wc = &wsm[c * 9];
        #pragma unroll
        for (int rr = 0; rr < 4; rr++) {
            int row = ty + rr * 8;
            float a = acc[rr];
            #pragma unroll
            for (int dy = 0; dy < 3; dy++)
                #pragma unroll
                for (int dx = 0; dx < 3; dx++)
                    a += s[row + dy][tx + dx] * wc[dy * 3 + dx];
            acc[rr] = a;
        }
    }
    float be = wsm[72];
    #pragma unroll
    for (int rr = 0; rr < 4; rr++) {
        int row = ty + rr * 8;
        d_u[(y0 + row) * N2 + x0 + tx] = acc[rr] + be;
    }
}

// ---------------- symmetrize + mask + key encode + hist1 (R9, measured) ----------
__global__ void k_symkey() {
    __shared__ float sB[64][65];
    __shared__ unsigned sh[4096];
    int tid = threadIdx.x;
    for (int i = tid; i < 4096; i += 256) sh[i] = 0u;
    int x0 = blockIdx.x * 64, y0 = blockIdx.y * 64;
    int ld = tid & 63, rr = tid >> 6;
    for (int r = rr; r < 64; r += 4)
        sB[r][ld] = d_u[(x0 + r) * N2 + y0 + ld];
    __syncthreads();
    float db = d_cw[73];
    unsigned NEGK = ~__float_as_uint(-1e30f);
    unsigned neg = 0;
    for (int r = rr; r < 64; r += 4) {
        int i = y0 + r, j = x0 + ld;
        float a  = d_u[i * N2 + j];
        float bt = sB[ld][r];                 // u[j][i]
        float w  = 0.5f * (a + bt) + db;
        float m  = (w > 0.f) ? w : -1e30f;
        unsigned bits = __float_as_uint(m);
        unsigned key  = ((int)bits < 0) ? ~bits : (bits | 0x80000000u);
        d_keys[i * N2 + j] = key;
        if (key == NEGK) neg++;
        else atomicAdd(&sh[key >> 20], 1u);
    }
    if (neg) atomicAdd(&sh[NEGK >> 20], neg);
    __syncthreads();
    for (int b = tid; b < 4096; b += 256) {
        unsigned c = sh[b];
        if (c) atomicAdd(&d_hist1[b], c);
    }
}

// ---------------- descending-cumulative threshold pick (mode 0/1) ----------------
__global__ void k_choose(int mode, unsigned Kv) {
    __shared__ unsigned ts[1024];
    const unsigned* hist = mode ? d_hist2 : d_hist1;
    int t = threadIdx.x;
    unsigned target = (mode == 0) ? Kv : d_sel[1];
    unsigned r[4]; unsigned lsum = 0;
    #pragma unroll
    for (int jj = 0; jj < 4; jj++) { r[jj] = hist[4095 - (t * 4 + jj)]; lsum += r[jj]; }
    ts[t] = lsum; __syncthreads();
    for (int off = 1; off < 1024; off <<= 1) {
        unsigned v = (t >= off) ? ts[t - off] : 0u;
        __syncthreads();
        ts[t] += v;
        __syncthreads();
    }
    unsigned run = ts[t] - lsum;
    #pragma unroll
    for (int jj = 0; jj < 4; jj++) {
        unsigned prev = run; run += r[jj];
        if (prev < target && run >= target) {
            unsigned b = 4095 - (t * 4 + jj);
            if (mode == 0) { d_sel[0] = b; d_sel[1] = target - prev; }
            else           { unsigned b1 = d_sel[0]; d_sel[2] = ((b1 << 12) | b) << 8; }
        }
    }
}

// ---------------- second-level histogram (R9, measured) ----------------
__global__ void k_hist2() {
    unsigned b1 = d_sel[0];
    int base = blockIdx.x * 2048 + threadIdx.x;
    #pragma unroll
    for (int i = 0; i < 8; i++) {
        unsigned key = d_keys[base + i * 256];
        if ((key >> 20) == b1) atomicAdd(&d_hist2[(key >> 8) & 0xFFFu], 1u);
    }
}

// ---------------- ordered compaction: count / scan / write (R9) ----------------
__global__ void k_ccount() {
    unsigned thr = d_sel[2];
    int w = blockIdx.x * 8 + (threadIdx.x >> 5);
    int lane = threadIdx.x & 31;
    int base = w * 1024 + lane;
    unsigned cnt = 0;
    #pragma unroll 8
    for (int r = 0; r < 32; r++) cnt += (d_keys[base + r * 32] >= thr) ? 1u : 0u;
    cnt = __reduce_add_sync(0xffffffffu, cnt);
    if (lane == 0) d_warpCnt[w] = cnt;
}

__global__ void k_cscan() {
    __shared__ unsigned ts[1024];
    int t = threadIdx.x;
    unsigned r[4], l = 0;
    #pragma unroll
    for (int jj = 0; jj < 4; jj++) { r[jj] = d_warpCnt[t * 4 + jj]; l += r[jj]; }
    ts[t] = l; __syncthreads();
    for (int off = 1; off < 1024; off <<= 1) {
        unsigned v = (t >= off) ? ts[t - off] : 0u;
        __syncthreads();
        ts[t] += v;
        __syncthreads();
    }
    unsigned base = ts[t] - l;
    #pragma unroll
    for (int jj = 0; jj < 4; jj++) { d_warpOff[t * 4 + jj] = base; base += r[jj]; }
    if (t == 1023) d_sel[3] = (base > CAP) ? CAP : base;
}

// only change vs R9: also record slot payload + slot->pixel map
__global__ void k_cwrite() {
    unsigned thr = d_sel[2];
    int w = blockIdx.x * 8 + (threadIdx.x >> 5);
    int lane = threadIdx.x & 31;
    unsigned run = d_warpOff[w];
    int base = w * 1024;
    for (int r = 0; r < 32; r++) {
        int e = base + r * 32 + lane;
        unsigned key = d_keys[e];
        bool p = key >= thr;
        unsigned mask = __ballot_sync(0xffffffffu, p);
        if (p) {
            unsigned pos = run + __popc(mask & ((1u << lane) - 1u));
            if (pos < CAP) {
                d_ci[0][pos] = ~key;
                d_cx[0][pos] = pos;           // payload = slot
                d_cpix[pos]  = (unsigned)e;   // slot -> pixel
            }
        }
        run += __popc(mask);
    }
}

// ---------------- reference-faithful evaluation (verified bit-exact R8-R14) --------
__device__ __forceinline__ float ldpix(const float* __restrict__ rel, int c, int y, int x) {
    bool ok = ((unsigned)y < N2) & ((unsigned)x < N2);
    int yy = ok ? y : 0;
    int xx = ok ? x : 0;
    float v = __ldg(&rel[(size_t)c * NPIX + yy * N2 + xx]);
    return ok ? v : 0.f;
}

__device__ __forceinline__ void faithful_eval(
    const float* __restrict__ rel,
    const float* w0s, const float* w1s,
    const float* bsm, const float* wssm, const float* bssm,
    int i, int j, float sym[8], float* l0o, float* l1o)
{
    float accA[8], accB[8];
    #pragma unroll
    for (int e = 0; e < 8; e++) { accA[e] = 0.f; accB[e] = 0.f; }
    #pragma unroll
    for (int dy = 0; dy < 3; dy++) {
        #pragma unroll
        for (int dx = 0; dx < 3; dx++) {
            int y1 = i + dy - 1, x1 = j + dx - 1;
            int y2 = j + dy - 1, x2 = i + dx - 1;
            #pragma unroll
            for (int c = 0; c < 8; c++) {
                float v1 = ldpix(rel, c, y1, x1);
                float v2 = ldpix(rel, c, y2, x2);
                int tap = (dy * 3 + dx) * 8 + c;
                #pragma unroll
                for (int e = 0; e < 4; e++) {
                    accA[e]     = fmaf(v1, w0s[e * 72 + tap], accA[e]);
                    accA[4 + e] = fmaf(v1, w1s[e * 72 + tap], accA[4 + e]);
                    accB[e]     = fmaf(v2, w0s[e * 72 + tap], accB[e]);
                    accB[4 + e] = fmaf(v2, w1s[e * 72 + tap], accB[4 + e]);
                }
            }
        }
    }
    #pragma unroll
    for (int e = 0; e < 8; e++) {
        float sA = accA[e] + bsm[e];
        float sB = accB[e] + bsm[e];
        sym[e] = (sA + sB) * 0.5f;
    }
    float l0 = 0.f, l1 = 0.f;
    #pragma unroll
    for (int e = 0; e < 8; e++) l0 = fmaf(sym[e], wssm[e], l0);
    l0 = l0 + bssm[0];
    #pragma unroll
    for (int e = 0; e < 8; e++) l1 = fmaf(sym[e], wssm[8 + e], l1);
    l1 = l1 + bssm[1];
    *l0o = l0; *l1o = l1;
}

__device__ __forceinline__ void load_weights_sw(
    const float* __restrict__ w0, const float* __restrict__ w1,
    const float* __restrict__ b0, const float* __restrict__ b1,
    const float* __restrict__ ws, const float* __restrict__ bs,
    float* w0s, float* w1s, float* bsm, float* wssm, float* bssm, int tid, int nthr)
{
    for (int t = tid; t < 288; t += nthr) {
        int e = t / 72, r = t - e * 72;
        int dyx = r >> 3, c = r & 7;
        int src = e * 72 + c * 9 + dyx;
        w0s[t] = w0[src];
        w1s[t] = w1[src];
    }
    if (tid < 4)  { bsm[tid] = b0[tid]; bsm[4 + tid] = b1[tid]; }
    if (tid >= 4 && tid < 20) wssm[tid - 4] = ws[tid - 4];
    if (tid >= 20 && tid < 22) bssm[tid - 20] = bs[tid - 20];
}

// rewrite candidate keys with exact values; store sym[8] per slot for emit
__global__ void k_refine(const float* __restrict__ rel,
                         const float* __restrict__ w0, const float* __restrict__ b0,
                         const float* __restrict__ w1, const float* __restrict__ b1,
                         const float* __restrict__ ws, const float* __restrict__ bs) {
    __shared__ float w0s[288], w1s[288], bsm[8], wssm[16], bssm[2];
    int tid = threadIdx.x;
    load_weights_sw(w0, w1, b0, b1, ws, bs, w0s, w1s, bsm, wssm, bssm, tid, 128);
    __syncthreads();
    unsigned C = d_sel[3];
    unsigned k = blockIdx.x * 128 + tid;
    if (k >= C) return;
    unsigned idx = d_cpix[k];
    int i = (int)(idx >> 11), j = (int)(idx & 2047u);
    float sym[8], l0, l1;
    faithful_eval(rel, w0s, w1s, bsm, wssm, bssm, i, j, sym, &l0, &l1);
    float v = (l1 > l0) ? (l1 - l0) : -1e30f;
    unsigned bits = __float_as_uint(v);
    unsigned key  = ((int)bits < 0) ? ~bits : (bits | 0x80000000u);
    d_ci[0][k] = ~key;
    #pragma unroll
    for (int e = 0; e < 8; e++) d_csym[k * 8 + e] = sym[e];
}

// ---------------- stable LSD radix sort (R9: 4 x 8-bit, 12 launches) ----------------
__global__ void k_rhist(int p, int s) {
    __shared__ unsigned sh[8][256];
    int warp = threadIdx.x >> 5, lane = threadIdx.x & 31;
    for (int d = lane; d < 256; d += 32) sh[warp][d] = 0u;
    __syncwarp();
    unsigned C = d_sel[3];
    int w = blockIdx.x * 8 + warp;
    unsigned base = (unsigned)w * 512u;
    for (int r = 0; r < 16; r++) {
        unsigned e = base + r * 32 + lane;
        if (e < C) {
            unsigned d = (d_ci[s][e] >> (p * 8)) & 255u;
            atomicAdd(&sh[warp][d], 1u);
        }
    }
    __syncwarp();
    for (int d = lane; d < 256; d += 32) d_wh[w * 256 + d] = sh[warp][d];
}

__global__ void k_rscan() {
    __shared__ unsigned ts[256];
    int t = threadIdx.x;
    unsigned tot = 0;
    for (int w = 0; w < RW; w++) tot += d_wh[w * 256 + t];
    ts[t] = tot; __syncthreads();
    for (int off = 1; off < 256; off <<= 1) {
        unsigned v = (t >= off) ? ts[t - off] : 0u;
        __syncthreads();
        ts[t] += v;
        __syncthreads();
    }
    unsigned run = ts[t] - tot;
    for (int w = 0; w < RW; w++) { d_woff[w * 256 + t] = run; run += d_wh[w * 256 + t]; }
}

__global__ void k_rscat(int p, int s) {
    __shared__ unsigned off[8][256];
    int warp = threadIdx.x >> 5, lane = threadIdx.x & 31;
    int w = blockIdx.x * 8 + warp;
    for (int d = lane; d < 256; d += 32) off[warp][d] = d_woff[w * 256 + d];
    __syncwarp();
    unsigned C = d_sel[3];
    unsigned base = (unsigned)w * 512u;
    int ds = 1 - s;
    for (int r = 0; r < 16; r++) {
        unsigned e = base + r * 32 + lane;
        bool act = (e < C);
        unsigned inv = 0, d = 0, idx = 0;
        if (act) { inv = d_ci[s][e]; idx = d_cx[s][e]; d = (inv >> (p * 8)) & 255u; }
        unsigned mv = act ? d : (0x100u | (unsigned)lane);
        unsigned mask = __match_any_sync(0xffffffffu, mv);
        unsigned rank = __popc(mask & ((1u << lane) - 1u));
        unsigned dst = 0;
        if (act) dst = off[warp][d] + rank;
        __syncwarp();
        if (act && rank == 0) off[warp][d] += __popc(mask);
        __syncwarp();
        if (act) { d_ci[ds][dst] = inv; d_cx[ds][dst] = idx; }
    }
}

// ---------------- emit: pure gather (sym precomputed in refine) ----------------
__global__ void k_emit(float* __restrict__ out, int K) {
    int k = blockIdx.x * 128 + threadIdx.x;
    if (k >= K) return;
    unsigned inv = d_ci[0][k];
    unsigned key = ~inv;
    float val = (key & 0x80000000u) ? __uint_as_float(key ^ 0x80000000u)
                                    : __uint_as_float(~key);
    unsigned slot = d_cx[0][k];
    unsigned idx  = d_cpix[slot];
    int i = (int)(idx >> 11), j = (int)(idx & 2047u);
    out[k]         = (float)i;
    out[K + k]     = (float)j;
    out[2 * K + k] = val;
    #pragma unroll
    for (int e = 0; e < 8; e++)
        out[3 * K + e * K + k] = d_csym[slot * 8 + e];
}

// ---------------- launch ----------------
extern "C" void kernel_launch(void* const* d_in, const int* in_sizes, int n_in,
                              void* d_out, int out_size) {
    const float* rel = (const float*)d_in[0];
    const float* w0  = (const float*)d_in[1];
    const float* b0  = (const float*)d_in[2];
    const float* w1  = (const float*)d_in[3];
    const float* b1  = (const float*)d_in[4];
    const float* ws  = (const float*)d_in[5];
    const float* bs  = (const float*)d_in[6];
    float* out = (float*)d_out;
    int K = out_size / 11;                    // [2,K]+[K]+[8,K] = 11K floats

    k_init<<<9, 1024>>>(ws, bs, w0, b0, w1, b1);
    k_conv<<<dim3(64, 64), dim3(32, 8)>>>(rel);
    k_symkey<<<dim3(32, 32), 256>>>();
    k_choose<<<1, 1024>>>(0, (unsigned)(K + MARGIN));
    k_hist2<<<2048, 256>>>();
    k_choose<<<1, 1024>>>(1, 0u);
    k_ccount<<<512, 256>>>();
    k_cscan<<<1, 1024>>>();
    k_cwrite<<<512, 256>>>();
    k_refine<<<(CAP + 127) / 128, 128>>>(rel, w0, b0, w1, b1, ws, bs);
    int s = 0;
    for (int p = 0; p < 4; p++) {
        k_rhist<<<16, 256>>>(p, s);
        k_rscan<<<1, 256>>>();
        k_rscat<<<16, 256>>>(p, s);
        s = 1 - s;
    }
    k_emit<<<(K + 127) / 128, 128>>>(out, K);
}